// round 15
// baseline (speedup 1.0000x reference)
#include <cuda_runtime.h>

// ---------------------------------------------------------------------------
// LCA layer on GB300 (FFMA2 path; tcgen05 unavailable: harness compiles
// device code as sm_103 without the 'a' suffix and ptxas rejects tcgen05).
//
// b = conv2d(x, D, s=4, p=2); 10x { inh = conv(convT(a)) - a;
//   u += 0.1*(b - u - inh); a = softshrink(u, 0.1) }
//
// conv∘convT == Gram operator: 3x3 taps, G[t][n][m] 64x64 per tap, center
// diag -1 folded. Boundary phantom products collapse to 1-D 3-tap edge Grams
// CT/CB/CL/CR + 4 corner overlaps CO, fused into lca_iter.
//
// lca_iter (v6): v5 tiling (ty-major taps), av register window rotated
// (load av[2..5], append av[1], av[0]; identical FFMA2 order) to cut peak
// live regs, and __launch_bounds__(128, 5) to fit 5 blocks/SM (102 regs):
// 5 warps/SMSP covers the LDS-latency exposure and shrinks the 4th-wave
// tail (1792 blocks / 740 concurrent = 2.42 waves vs 3.03/4).
// ---------------------------------------------------------------------------

#define NATOMS 64
#define BATCH  64
#define H 56
#define W 56
#define HW (H*W)
#define PLANE ((size_t)NATOMS * HW)

__device__ float g_B [BATCH * NATOMS * HW];
__device__ float g_U [BATCH * NATOMS * HW];
__device__ float g_A0[BATCH * NATOMS * HW];
__device__ float g_G [9 * 64 * 64];            // interior Gram [tap][n][m]
__device__ float g_CT[3 * 64 * 64];            // top edge, taps dx=-1,0,1
__device__ float g_CB[3 * 64 * 64];            // bottom
__device__ float g_CL[3 * 64 * 64];            // left,  taps dy=-1,0,1
__device__ float g_CR[3 * 64 * 64];            // right
__device__ float g_CO[4 * 64 * 64];            // corner overlaps TL,TR,BL,BR

// ---- packed f32x2 helpers --------------------------------------------------
__device__ __forceinline__ unsigned long long dup2(float x) {
    unsigned long long r;
    asm("mov.b64 %0, {%1, %1};" : "=l"(r) : "f"(x));
    return r;
}
__device__ __forceinline__ void ffma2(unsigned long long& d,
                                      unsigned long long a,
                                      unsigned long long b) {
    asm("fma.rn.f32x2 %0, %1, %2, %0;" : "+l"(d) : "l"(a), "l"(b));
}
__device__ __forceinline__ float2 unpk(unsigned long long v) {
    float2 r;
    asm("mov.b64 {%0, %1}, %2;" : "=f"(r.x), "=f"(r.y) : "l"(v));
    return r;
}
__device__ __forceinline__ float shrinkf(float u) {
    float mag = fabsf(u) - 0.1f;
    return mag > 0.0f ? copysignf(mag, u) : 0.0f;
}

// ---------------------------------------------------------------------------
// Gram kernel. 25 blocks: 0..8 interior taps, 9..20 edges, 21..24 corners.
// ---------------------------------------------------------------------------
__global__ void lca_gram(const float* __restrict__ dict) {
    __shared__ float ds[64 * 3 * 8 * 8];
    const int t   = blockIdx.x;
    const int tid = threadIdx.x;
    for (int e = tid; e < 12288; e += 256) ds[e] = dict[e];
    __syncthreads();

    if (t < 9) {
        const int dy = t / 3 - 1, dx = t % 3 - 1;
        const int kylo = dy < 0 ? 4 : 0, kyhi = dy > 0 ? 4 : 8;
        const int kxlo = dx < 0 ? 4 : 0, kxhi = dx > 0 ? 4 : 8;
        for (int e = tid; e < 4096; e += 256) {
            const int n = e >> 6, m = e & 63;
            float s = 0.0f;
            for (int i = 0; i < 3; ++i) {
                const float* dm = &ds[m * 192 + i * 64];
                const float* dn = &ds[n * 192 + i * 64 + 4 * dy * 8 + 4 * dx];
                for (int ky = kylo; ky < kyhi; ++ky)
                    #pragma unroll
                    for (int kx = kxlo; kx < kxhi; ++kx)
                        s += dm[ky * 8 + kx] * dn[ky * 8 + kx];
            }
            if (t == 4 && n == m) s -= 1.0f;
            g_G[t * 4096 + e] = s;
        }
    } else if (t < 21) {
        const int side = (t - 9) / 3;           // 0 top,1 bot,2 left,3 right
        const int j    = (t - 9) % 3;
        const int d    = j - 1;
        float* out = (side == 0 ? g_CT : side == 1 ? g_CB
                    : side == 2 ? g_CL : g_CR) + j * 4096;
        for (int e = tid; e < 4096; e += 256) {
            const int n = e >> 6, m = e & 63;
            float s = 0.0f;
            for (int i = 0; i < 3; ++i) {
                const float* dm = &ds[m * 192 + i * 64];
                const float* dn = &ds[n * 192 + i * 64];
                if (side < 2) {
                    const int ky0 = (side == 0) ? 0 : 6;
                    const int kxlo = d < 0 ? 4 : 0, kxhi = d > 0 ? 4 : 8;
                    for (int ky = ky0; ky < ky0 + 2; ++ky)
                        for (int kx = kxlo; kx < kxhi; ++kx)
                            s += dm[ky * 8 + kx] * dn[ky * 8 + kx + 4 * d];
                } else {
                    const int kx0 = (side == 2) ? 0 : 6;
                    const int kylo = d < 0 ? 4 : 0, kyhi = d > 0 ? 4 : 8;
                    for (int ky = kylo; ky < kyhi; ++ky)
                        for (int kx = kx0; kx < kx0 + 2; ++kx)
                            s += dm[ky * 8 + kx] * dn[(ky + 4 * d) * 8 + kx];
                }
            }
            out[e] = s;
        }
    } else {
        const int c   = t - 21;
        const int ky0 = (c < 2) ? 0 : 6;
        const int kx0 = (c & 1) ? 6 : 0;
        for (int e = tid; e < 4096; e += 256) {
            const int n = e >> 6, m = e & 63;
            float s = 0.0f;
            for (int i = 0; i < 3; ++i) {
                const float* dm = &ds[m * 192 + i * 64];
                const float* dn = &ds[n * 192 + i * 64];
                for (int ky = ky0; ky < ky0 + 2; ++ky)
                    for (int kx = kx0; kx < kx0 + 2; ++kx)
                        s += dm[ky * 8 + kx] * dn[ky * 8 + kx];
            }
            g_CO[c * 4096 + e] = s;
        }
    }
}

// ---------------------------------------------------------------------------
// b = conv2d(x, D, 4, 2), fused iter 1: u1 = 0.1*b, a1 = shrink(u1).
// (v2, passing: phase-split x-patch, warp-uniform dict.)
// ---------------------------------------------------------------------------
__global__ __launch_bounds__(128, 4)
void lca_b(const float* __restrict__ x, const float* __restrict__ dict) {
    __shared__ float xs[4 * 36 * 19];            // 10.7 KB (phase arrays)
    __shared__ float dt[64 * 68];                // 17.0 KB [kk][m] stride 68

    const int bi   = blockIdx.y;
    const int tile = blockIdx.x;                 // 0..27
    const int ty0  = (tile >> 2) * 8;
    const int tx0  = (tile & 3) * 16;
    const int tid  = threadIdx.x;
    const int w    = tid >> 5, l = tid & 31;
    const int m0   = w * 16;
    const int py   = l >> 2, xq = l & 3;

    unsigned long long acc[4][8];
    #pragma unroll
    for (int j = 0; j < 4; ++j)
        #pragma unroll
        for (int c = 0; c < 8; ++c) acc[j][c] = 0ull;

    for (int i = 0; i < 3; ++i) {
        __syncthreads();
        for (int e = tid; e < 4096; e += 128) {
            const int m = e >> 6, kk = e & 63;
            dt[kk * 68 + m] = dict[m * 192 + i * 64 + kk];
        }
        const int gy0 = 4 * ty0 - 2, gx0 = 4 * tx0 - 2;
        for (int e = tid; e < 2448; e += 128) {
            const int r = e / 68, cc = e - r * 68;
            const int gy = gy0 + r, gx = gx0 + cc;
            float v = 0.0f;
            if ((unsigned)gy < 224u && (unsigned)gx < 224u)
                v = x[((size_t)(bi * 3 + i) * 224 + gy) * 224 + gx];
            const int p  = (cc + 2) & 3;
            const int tc = (cc - 2 - p) / 4 + 1;
            xs[p * 684 + r * 19 + tc] = v;
        }
        __syncthreads();

        const float* xsp = xs + (4 * py) * 19 + xq + 1;
        for (int ky = 0; ky < 8; ++ky) {
            const float* xrow = xsp + ky * 19;
            #pragma unroll
            for (int kx = 0; kx < 8; ++kx) {
                const int p = (kx + 2) & 3;          // (kx-2) mod 4
                const int q = (kx < 2) ? -1 : (kx < 6) ? 0 : 1;
                const float* xr = xrow + p * 684 + q;
                const float* gt = &dt[(ky * 8 + kx) * 68 + m0]; // warp-uniform
                ulonglong2 H0 = *reinterpret_cast<const ulonglong2*>(gt + 0);
                ulonglong2 H1 = *reinterpret_cast<const ulonglong2*>(gt + 4);
                ulonglong2 H2 = *reinterpret_cast<const ulonglong2*>(gt + 8);
                ulonglong2 H3 = *reinterpret_cast<const ulonglong2*>(gt + 12);
                #pragma unroll
                for (int j = 0; j < 4; ++j) {
                    const unsigned long long a = dup2(xr[4 * j]);
                    ffma2(acc[j][0], a, H0.x); ffma2(acc[j][1], a, H0.y);
                    ffma2(acc[j][2], a, H1.x); ffma2(acc[j][3], a, H1.y);
                    ffma2(acc[j][4], a, H2.x); ffma2(acc[j][5], a, H2.y);
                    ffma2(acc[j][6], a, H3.x); ffma2(acc[j][7], a, H3.y);
                }
            }
        }
    }

    const int y = ty0 + py;
    #pragma unroll
    for (int j = 0; j < 4; ++j) {
        const int xg = tx0 + xq + 4 * j;
        if (xg < 56) {
            float bv[16];
            #pragma unroll
            for (int c = 0; c < 8; ++c) {
                float2 t = unpk(acc[j][c]);
                bv[2 * c] = t.x; bv[2 * c + 1] = t.y;
            }
            #pragma unroll
            for (int mm = 0; mm < 16; ++mm) {
                const size_t idx =
                    ((size_t)(bi * 64 + m0 + mm) * H + y) * W + xg;
                const float bb = bv[mm];
                const float un = 0.1f * bb;
                g_B[idx]  = bb;
                g_U[idx]  = un;
                g_A0[idx] = shrinkf(un);
            }
        }
    }
}

// ---------------------------------------------------------------------------
// One LCA iteration, fused border correction (v6: av window + 5 blk/SM).
// ---------------------------------------------------------------------------
__global__ __launch_bounds__(128, 5)
void lca_iter(float* __restrict__ a_ext, int mode) {
    __shared__ float gs [8 * 9 * 64];            // [nl*9+tap][m]   18.4 KB
    __shared__ float ash[8 * 10 * 21];           // [nl][r][c<18]    6.7 KB
    __shared__ float corrH[16][64];              // [local x][m]     4.0 KB
    __shared__ float corrV[8][64];               // [py][m]          2.0 KB

    const float* __restrict__ a_in  = mode ? a_ext : g_A0;
    float* __restrict__       a_out = mode ? g_A0  : a_ext;

    const int bi   = blockIdx.y;
    const int tile = blockIdx.x;                 // 0..27
    const int ty0  = (tile >> 2) * 8;
    const int tx0  = (tile & 3) * 16;
    const int tid  = threadIdx.x;
    const int w    = tid >> 5, l = tid & 31;
    const int m0   = w * 16;
    const int py   = l >> 2, xq = l & 3, x0 = 4 * xq;

    const bool top = (ty0 == 0), bot = (ty0 == 48);
    const bool lef = (tx0 == 0), rig = (tx0 == 48);
    const bool hE = top || bot, vE = lef || rig;

    if (hE || vE) {
        for (int e = tid; e < 1024; e += 128) (&corrH[0][0])[e] = 0.0f;
        for (int e = tid; e < 512;  e += 128) (&corrV[0][0])[e] = 0.0f;
    }

    unsigned long long acc[4][8];
    #pragma unroll
    for (int j = 0; j < 4; ++j)
        #pragma unroll
        for (int c = 0; c < 8; ++c) acc[j][c] = 0ull;

    const float* abase = a_in + (size_t)bi * PLANE;

    for (int ck = 0; ck < 8; ++ck) {
        const int ch0 = ck * 8;
        __syncthreads();                              // prev chunk consumed
        // G slice [nl*9+tap][m], float4-staged
        for (int e = tid; e < 1152; e += 128) {
            const int m4 = e & 15, q = e >> 4;        // q = nl*9+tap
            const int nl = q / 9, tap = q - nl * 9;
            reinterpret_cast<float4*>(gs)[e] =
                reinterpret_cast<const float4*>(
                    g_G + tap * 4096 + (ch0 + nl) * 64)[m4];
        }
        // a halo: 10 rows x 18 cols per channel, zero outside image
        for (int e = tid; e < 1440; e += 128) {
            const int nl = e / 180, r2 = e - nl * 180;
            const int rr = r2 / 18, cc = r2 - rr * 18;
            const int gy = ty0 - 1 + rr, gx = tx0 - 1 + cc;
            float v = 0.0f;
            if ((unsigned)gy < (unsigned)H && (unsigned)gx < (unsigned)W)
                v = abase[(ch0 + nl) * HW + gy * W + gx];
            ash[nl * 210 + rr * 21 + cc] = v;
        }
        __syncthreads();

        for (int nl = 0; nl < 8; ++nl) {
            const float* ap = &ash[nl * 210 + py * 21 + x0];
            const float* gp = &gs[nl * 576 + m0];
            #pragma unroll
            for (int ty_ = 0; ty_ < 3; ++ty_) {
                const float* arow = ap + (2 - ty_) * 21;
                // av window: tx=0 needs av[2..5]; tx=1 appends av[1];
                // tx=2 appends av[0]. Same FFMA2 order as v5 (bit-identical).
                unsigned long long a2 = dup2(arow[2]);
                unsigned long long a3 = dup2(arow[3]);
                unsigned long long a4 = dup2(arow[4]);
                unsigned long long a5 = dup2(arow[5]);
                unsigned long long a1, a0;
                #pragma unroll
                for (int tx_ = 0; tx_ < 3; ++tx_) {
                    const float* gt = gp + (ty_ * 3 + tx_) * 64; // warp-uniform
                    ulonglong2 H0 = *reinterpret_cast<const ulonglong2*>(gt + 0);
                    ulonglong2 H1 = *reinterpret_cast<const ulonglong2*>(gt + 4);
                    ulonglong2 H2 = *reinterpret_cast<const ulonglong2*>(gt + 8);
                    ulonglong2 H3 = *reinterpret_cast<const ulonglong2*>(gt + 12);
                    unsigned long long opnd[4];
                    if (tx_ == 0) {
                        opnd[0] = a2; opnd[1] = a3; opnd[2] = a4; opnd[3] = a5;
                    } else if (tx_ == 1) {
                        a1 = dup2(arow[1]);
                        opnd[0] = a1; opnd[1] = a2; opnd[2] = a3; opnd[3] = a4;
                    } else {
                        a0 = dup2(arow[0]);
                        opnd[0] = a0; opnd[1] = a1; opnd[2] = a2; opnd[3] = a3;
                    }
                    #pragma unroll
                    for (int j = 0; j < 4; ++j) {
                        const unsigned long long a = opnd[j];
                        ffma2(acc[j][0], a, H0.x); ffma2(acc[j][1], a, H0.y);
                        ffma2(acc[j][2], a, H1.x); ffma2(acc[j][3], a, H1.y);
                        ffma2(acc[j][4], a, H2.x); ffma2(acc[j][5], a, H2.y);
                        ffma2(acc[j][6], a, H3.x); ffma2(acc[j][7], a, H3.y);
                    }
                }
            }
        }

        // ---- border correction accumulation (edge blocks only) ------------
        if (hE) {
            const float* __restrict__ C = top ? g_CT : g_CB;
            const int er = top ? 1 : 8;
            const int m = tid >> 1, p0 = (tid & 1) * 8;
            float c[8];
            #pragma unroll
            for (int k = 0; k < 8; ++k) c[k] = 0.0f;
            for (int j = 0; j < 3; ++j)
                #pragma unroll
                for (int nl = 0; nl < 8; ++nl) {
                    const float cv = C[j * 4096 + (ch0 + nl) * 64 + m];
                    const float* arow = &ash[nl * 210 + er * 21 + p0 + 2 - j];
                    #pragma unroll
                    for (int k = 0; k < 8; ++k) c[k] += cv * arow[k];
                }
            #pragma unroll
            for (int k = 0; k < 8; ++k) corrH[p0 + k][m] += c[k];
        }
        if (vE) {
            const float* __restrict__ C = lef ? g_CL : g_CR;
            const int ec = lef ? 1 : 8;
            const int m = tid >> 1, p0 = (tid & 1) * 4;
            float c0 = 0.f, c1 = 0.f, c2 = 0.f, c3 = 0.f;
            for (int j = 0; j < 3; ++j)
                #pragma unroll
                for (int nl = 0; nl < 8; ++nl) {
                    const float cv = C[j * 4096 + (ch0 + nl) * 64 + m];
                    const float* acol = &ash[nl * 210 + (p0 + 2 - j) * 21 + ec];
                    c0 += cv * acol[0];
                    c1 += cv * acol[21];
                    c2 += cv * acol[42];
                    c3 += cv * acol[63];
                }
            corrV[p0 + 0][m] += c0; corrV[p0 + 1][m] += c1;
            corrV[p0 + 2][m] += c2; corrV[p0 + 3][m] += c3;
        }
        if (hE && vE) {
            const int m = tid >> 1;
            const int half = tid & 1;
            const int want = rig ? 1 : 0;
            if (half == want) {
                const int c = (top ? 0 : 2) + (rig ? 1 : 0);
                const int rr = top ? 1 : 8, cc2 = lef ? 1 : 8;
                float s = 0.f;
                #pragma unroll
                for (int nl = 0; nl < 8; ++nl)
                    s += g_CO[c * 4096 + (ch0 + nl) * 64 + m]
                       * ash[nl * 210 + rr * 21 + cc2];
                corrH[rig ? 7 : 0][m] -= s;
            }
        }
    }
    __syncthreads();                                  // corr complete

    // ---- epilogue: fused u update + shrink ---------------------------------
    const int xg = tx0 + x0;                          // global x of quad start
    if (xg < 56) {
        float ga[4][16];
        #pragma unroll
        for (int j = 0; j < 4; ++j)
            #pragma unroll
            for (int c = 0; c < 8; ++c) {
                float2 t = unpk(acc[j][c]);
                ga[j][2 * c] = t.x; ga[j][2 * c + 1] = t.y;
            }

        if ((top && py == 0) || (bot && py == 7)) {
            #pragma unroll
            for (int j = 0; j < 4; ++j)
                #pragma unroll
                for (int mi = 0; mi < 16; ++mi)
                    ga[j][mi] -= corrH[x0 + j][m0 + mi];
        }
        if (lef && xq == 0) {
            #pragma unroll
            for (int mi = 0; mi < 16; ++mi) ga[0][mi] -= corrV[py][m0 + mi];
        }
        if (rig && xq == 1) {                         // local x 7 = global 55
            #pragma unroll
            for (int mi = 0; mi < 16; ++mi) ga[3][mi] -= corrV[py][m0 + mi];
        }

        const int y = ty0 + py;
        #pragma unroll
        for (int mi = 0; mi < 16; ++mi) {
            const size_t base = ((size_t)(bi * 64 + m0 + mi) * H + y) * W + xg;
            float4 u4 = *reinterpret_cast<const float4*>(&g_U[base]);
            float4 b4 = *reinterpret_cast<const float4*>(&g_B[base]);
            float4 un, an;
            un.x = u4.x + 0.1f * (b4.x - u4.x - ga[0][mi]);
            un.y = u4.y + 0.1f * (b4.y - u4.y - ga[1][mi]);
            un.z = u4.z + 0.1f * (b4.z - u4.z - ga[2][mi]);
            un.w = u4.w + 0.1f * (b4.w - u4.w - ga[3][mi]);
            an.x = shrinkf(un.x); an.y = shrinkf(un.y);
            an.z = shrinkf(un.z); an.w = shrinkf(un.w);
            *reinterpret_cast<float4*>(&g_U[base])   = un;
            *reinterpret_cast<float4*>(&a_out[base]) = an;
        }
    }
}

// ---------------------------------------------------------------------------
extern "C" void kernel_launch(void* const* d_in, const int* in_sizes, int n_in,
                              void* d_out, int out_size) {
    (void)in_sizes; (void)n_in; (void)out_size;
    const float* x    = (const float*)d_in[0];
    const float* dict = (const float*)d_in[1];
    float*       out  = (float*)d_out;

    lca_gram<<<25, 256>>>(dict);
    lca_b<<<dim3(28, 64), 128>>>(x, dict);

    // iterations 2..10; odd count -> final a lands in d_out
    for (int it = 0; it < 9; ++it)
        lca_iter<<<dim3(28, 64), 128>>>(out, it & 1);
}

// round 16
// speedup vs baseline: 1.0651x; 1.0651x over previous
#include <cuda_runtime.h>

// ---------------------------------------------------------------------------
// LCA layer on GB300 (FFMA2 path; tcgen05 unavailable: harness compiles
// device code as sm_103 without the 'a' suffix and ptxas rejects tcgen05).
//
// b = conv2d(x, D, s=4, p=2); 10x { inh = conv(convT(a)) - a;
//   u += 0.1*(b - u - inh); a = softshrink(u, 0.1) }
//
// conv∘convT == Gram operator: 3x3 taps, G[t][n][m] 64x64 per tap, center
// diag -1 folded. Boundary phantom products collapse to 1-D 3-tap edge Grams
// CT/CB/CL/CR + 4 corner overlaps CO, fused into lca_iter.
//
// lca_iter (v7): R14 tiling (ty-major, av[6], 128 regs, 4 blocks/SM) +
// software-pipelined G operand: Hcur in regs, Hnext prefetched one tap ahead
// (next nl's tap0 across nl boundaries; clamped dummy at the chunk tail so
// nothing is read across the restage barrier). Each G LDS.128 now sits >=64
// fma-cycles ahead of its consumers -> kills the per-tap LDS head stall that
// capped fma at 61.5%.
// ---------------------------------------------------------------------------

#define NATOMS 64
#define BATCH  64
#define H 56
#define W 56
#define HW (H*W)
#define PLANE ((size_t)NATOMS * HW)

__device__ float g_B [BATCH * NATOMS * HW];
__device__ float g_U [BATCH * NATOMS * HW];
__device__ float g_A0[BATCH * NATOMS * HW];
__device__ float g_G [9 * 64 * 64];            // interior Gram [tap][n][m]
__device__ float g_CT[3 * 64 * 64];            // top edge, taps dx=-1,0,1
__device__ float g_CB[3 * 64 * 64];            // bottom
__device__ float g_CL[3 * 64 * 64];            // left,  taps dy=-1,0,1
__device__ float g_CR[3 * 64 * 64];            // right
__device__ float g_CO[4 * 64 * 64];            // corner overlaps TL,TR,BL,BR

// ---- packed f32x2 helpers --------------------------------------------------
__device__ __forceinline__ unsigned long long dup2(float x) {
    unsigned long long r;
    asm("mov.b64 %0, {%1, %1};" : "=l"(r) : "f"(x));
    return r;
}
__device__ __forceinline__ void ffma2(unsigned long long& d,
                                      unsigned long long a,
                                      unsigned long long b) {
    asm("fma.rn.f32x2 %0, %1, %2, %0;" : "+l"(d) : "l"(a), "l"(b));
}
__device__ __forceinline__ float2 unpk(unsigned long long v) {
    float2 r;
    asm("mov.b64 {%0, %1}, %2;" : "=f"(r.x), "=f"(r.y) : "l"(v));
    return r;
}
__device__ __forceinline__ float shrinkf(float u) {
    float mag = fabsf(u) - 0.1f;
    return mag > 0.0f ? copysignf(mag, u) : 0.0f;
}

// ---------------------------------------------------------------------------
// Gram kernel. 25 blocks: 0..8 interior taps, 9..20 edges, 21..24 corners.
// ---------------------------------------------------------------------------
__global__ void lca_gram(const float* __restrict__ dict) {
    __shared__ float ds[64 * 3 * 8 * 8];
    const int t   = blockIdx.x;
    const int tid = threadIdx.x;
    for (int e = tid; e < 12288; e += 256) ds[e] = dict[e];
    __syncthreads();

    if (t < 9) {
        const int dy = t / 3 - 1, dx = t % 3 - 1;
        const int kylo = dy < 0 ? 4 : 0, kyhi = dy > 0 ? 4 : 8;
        const int kxlo = dx < 0 ? 4 : 0, kxhi = dx > 0 ? 4 : 8;
        for (int e = tid; e < 4096; e += 256) {
            const int n = e >> 6, m = e & 63;
            float s = 0.0f;
            for (int i = 0; i < 3; ++i) {
                const float* dm = &ds[m * 192 + i * 64];
                const float* dn = &ds[n * 192 + i * 64 + 4 * dy * 8 + 4 * dx];
                for (int ky = kylo; ky < kyhi; ++ky)
                    #pragma unroll
                    for (int kx = kxlo; kx < kxhi; ++kx)
                        s += dm[ky * 8 + kx] * dn[ky * 8 + kx];
            }
            if (t == 4 && n == m) s -= 1.0f;
            g_G[t * 4096 + e] = s;
        }
    } else if (t < 21) {
        const int side = (t - 9) / 3;           // 0 top,1 bot,2 left,3 right
        const int j    = (t - 9) % 3;
        const int d    = j - 1;
        float* out = (side == 0 ? g_CT : side == 1 ? g_CB
                    : side == 2 ? g_CL : g_CR) + j * 4096;
        for (int e = tid; e < 4096; e += 256) {
            const int n = e >> 6, m = e & 63;
            float s = 0.0f;
            for (int i = 0; i < 3; ++i) {
                const float* dm = &ds[m * 192 + i * 64];
                const float* dn = &ds[n * 192 + i * 64];
                if (side < 2) {
                    const int ky0 = (side == 0) ? 0 : 6;
                    const int kxlo = d < 0 ? 4 : 0, kxhi = d > 0 ? 4 : 8;
                    for (int ky = ky0; ky < ky0 + 2; ++ky)
                        for (int kx = kxlo; kx < kxhi; ++kx)
                            s += dm[ky * 8 + kx] * dn[ky * 8 + kx + 4 * d];
                } else {
                    const int kx0 = (side == 2) ? 0 : 6;
                    const int kylo = d < 0 ? 4 : 0, kyhi = d > 0 ? 4 : 8;
                    for (int ky = kylo; ky < kyhi; ++ky)
                        for (int kx = kx0; kx < kx0 + 2; ++kx)
                            s += dm[ky * 8 + kx] * dn[(ky + 4 * d) * 8 + kx];
                }
            }
            out[e] = s;
        }
    } else {
        const int c   = t - 21;
        const int ky0 = (c < 2) ? 0 : 6;
        const int kx0 = (c & 1) ? 6 : 0;
        for (int e = tid; e < 4096; e += 256) {
            const int n = e >> 6, m = e & 63;
            float s = 0.0f;
            for (int i = 0; i < 3; ++i) {
                const float* dm = &ds[m * 192 + i * 64];
                const float* dn = &ds[n * 192 + i * 64];
                for (int ky = ky0; ky < ky0 + 2; ++ky)
                    for (int kx = kx0; kx < kx0 + 2; ++kx)
                        s += dm[ky * 8 + kx] * dn[ky * 8 + kx];
            }
            g_CO[c * 4096 + e] = s;
        }
    }
}

// ---------------------------------------------------------------------------
// b = conv2d(x, D, 4, 2), fused iter 1: u1 = 0.1*b, a1 = shrink(u1).
// (v2, passing: phase-split x-patch, warp-uniform dict.)
// ---------------------------------------------------------------------------
__global__ __launch_bounds__(128, 4)
void lca_b(const float* __restrict__ x, const float* __restrict__ dict) {
    __shared__ float xs[4 * 36 * 19];            // 10.7 KB (phase arrays)
    __shared__ float dt[64 * 68];                // 17.0 KB [kk][m] stride 68

    const int bi   = blockIdx.y;
    const int tile = blockIdx.x;                 // 0..27
    const int ty0  = (tile >> 2) * 8;
    const int tx0  = (tile & 3) * 16;
    const int tid  = threadIdx.x;
    const int w    = tid >> 5, l = tid & 31;
    const int m0   = w * 16;
    const int py   = l >> 2, xq = l & 3;

    unsigned long long acc[4][8];
    #pragma unroll
    for (int j = 0; j < 4; ++j)
        #pragma unroll
        for (int c = 0; c < 8; ++c) acc[j][c] = 0ull;

    for (int i = 0; i < 3; ++i) {
        __syncthreads();
        for (int e = tid; e < 4096; e += 128) {
            const int m = e >> 6, kk = e & 63;
            dt[kk * 68 + m] = dict[m * 192 + i * 64 + kk];
        }
        const int gy0 = 4 * ty0 - 2, gx0 = 4 * tx0 - 2;
        for (int e = tid; e < 2448; e += 128) {
            const int r = e / 68, cc = e - r * 68;
            const int gy = gy0 + r, gx = gx0 + cc;
            float v = 0.0f;
            if ((unsigned)gy < 224u && (unsigned)gx < 224u)
                v = x[((size_t)(bi * 3 + i) * 224 + gy) * 224 + gx];
            const int p  = (cc + 2) & 3;
            const int tc = (cc - 2 - p) / 4 + 1;
            xs[p * 684 + r * 19 + tc] = v;
        }
        __syncthreads();

        const float* xsp = xs + (4 * py) * 19 + xq + 1;
        for (int ky = 0; ky < 8; ++ky) {
            const float* xrow = xsp + ky * 19;
            #pragma unroll
            for (int kx = 0; kx < 8; ++kx) {
                const int p = (kx + 2) & 3;          // (kx-2) mod 4
                const int q = (kx < 2) ? -1 : (kx < 6) ? 0 : 1;
                const float* xr = xrow + p * 684 + q;
                const float* gt = &dt[(ky * 8 + kx) * 68 + m0]; // warp-uniform
                ulonglong2 H0 = *reinterpret_cast<const ulonglong2*>(gt + 0);
                ulonglong2 H1 = *reinterpret_cast<const ulonglong2*>(gt + 4);
                ulonglong2 H2 = *reinterpret_cast<const ulonglong2*>(gt + 8);
                ulonglong2 H3 = *reinterpret_cast<const ulonglong2*>(gt + 12);
                #pragma unroll
                for (int j = 0; j < 4; ++j) {
                    const unsigned long long a = dup2(xr[4 * j]);
                    ffma2(acc[j][0], a, H0.x); ffma2(acc[j][1], a, H0.y);
                    ffma2(acc[j][2], a, H1.x); ffma2(acc[j][3], a, H1.y);
                    ffma2(acc[j][4], a, H2.x); ffma2(acc[j][5], a, H2.y);
                    ffma2(acc[j][6], a, H3.x); ffma2(acc[j][7], a, H3.y);
                }
            }
        }
    }

    const int y = ty0 + py;
    #pragma unroll
    for (int j = 0; j < 4; ++j) {
        const int xg = tx0 + xq + 4 * j;
        if (xg < 56) {
            float bv[16];
            #pragma unroll
            for (int c = 0; c < 8; ++c) {
                float2 t = unpk(acc[j][c]);
                bv[2 * c] = t.x; bv[2 * c + 1] = t.y;
            }
            #pragma unroll
            for (int mm = 0; mm < 16; ++mm) {
                const size_t idx =
                    ((size_t)(bi * 64 + m0 + mm) * H + y) * W + xg;
                const float bb = bv[mm];
                const float un = 0.1f * bb;
                g_B[idx]  = bb;
                g_U[idx]  = un;
                g_A0[idx] = shrinkf(un);
            }
        }
    }
}

// ---------------------------------------------------------------------------
// One LCA iteration, fused border correction (v7: G software pipeline).
// ---------------------------------------------------------------------------
__global__ __launch_bounds__(128, 4)
void lca_iter(float* __restrict__ a_ext, int mode) {
    __shared__ float gs [8 * 9 * 64];            // [nl*9+tap][m]   18.4 KB
    __shared__ float ash[8 * 10 * 21];           // [nl][r][c<18]    6.7 KB
    __shared__ float corrH[16][64];              // [local x][m]     4.0 KB
    __shared__ float corrV[8][64];               // [py][m]          2.0 KB

    const float* __restrict__ a_in  = mode ? a_ext : g_A0;
    float* __restrict__       a_out = mode ? g_A0  : a_ext;

    const int bi   = blockIdx.y;
    const int tile = blockIdx.x;                 // 0..27
    const int ty0  = (tile >> 2) * 8;
    const int tx0  = (tile & 3) * 16;
    const int tid  = threadIdx.x;
    const int w    = tid >> 5, l = tid & 31;
    const int m0   = w * 16;
    const int py   = l >> 2, xq = l & 3, x0 = 4 * xq;

    const bool top = (ty0 == 0), bot = (ty0 == 48);
    const bool lef = (tx0 == 0), rig = (tx0 == 48);
    const bool hE = top || bot, vE = lef || rig;

    if (hE || vE) {
        for (int e = tid; e < 1024; e += 128) (&corrH[0][0])[e] = 0.0f;
        for (int e = tid; e < 512;  e += 128) (&corrV[0][0])[e] = 0.0f;
    }

    unsigned long long acc[4][8];
    #pragma unroll
    for (int j = 0; j < 4; ++j)
        #pragma unroll
        for (int c = 0; c < 8; ++c) acc[j][c] = 0ull;

    const float* abase = a_in + (size_t)bi * PLANE;

    for (int ck = 0; ck < 8; ++ck) {
        const int ch0 = ck * 8;
        __syncthreads();                              // prev chunk consumed
        // G slice [nl*9+tap][m], float4-staged
        for (int e = tid; e < 1152; e += 128) {
            const int m4 = e & 15, q = e >> 4;        // q = nl*9+tap
            const int nl = q / 9, tap = q - nl * 9;
            reinterpret_cast<float4*>(gs)[e] =
                reinterpret_cast<const float4*>(
                    g_G + tap * 4096 + (ch0 + nl) * 64)[m4];
        }
        // a halo: 10 rows x 18 cols per channel, zero outside image
        for (int e = tid; e < 1440; e += 128) {
            const int nl = e / 180, r2 = e - nl * 180;
            const int rr = r2 / 18, cc = r2 - rr * 18;
            const int gy = ty0 - 1 + rr, gx = tx0 - 1 + cc;
            float v = 0.0f;
            if ((unsigned)gy < (unsigned)H && (unsigned)gx < (unsigned)W)
                v = abase[(ch0 + nl) * HW + gy * W + gx];
            ash[nl * 210 + rr * 21 + cc] = v;
        }
        __syncthreads();

        // preload Hcur = G[nl=0][tap=0] (warp-uniform)
        const float* g0 = &gs[m0];
        ulonglong2 C0 = *reinterpret_cast<const ulonglong2*>(g0 + 0);
        ulonglong2 C1 = *reinterpret_cast<const ulonglong2*>(g0 + 4);
        ulonglong2 C2 = *reinterpret_cast<const ulonglong2*>(g0 + 8);
        ulonglong2 C3 = *reinterpret_cast<const ulonglong2*>(g0 + 12);

        for (int nl = 0; nl < 8; ++nl) {
            const float* ap = &ash[nl * 210 + py * 21 + x0];
            const float* gp = &gs[nl * 576 + m0];
            #pragma unroll
            for (int ty_ = 0; ty_ < 3; ++ty_) {
                unsigned long long av[6];
                const float* arow = ap + (2 - ty_) * 21;
                #pragma unroll
                for (int c = 0; c < 6; ++c) av[c] = dup2(arow[c]);
                #pragma unroll
                for (int tx_ = 0; tx_ < 3; ++tx_) {
                    const int tap = ty_ * 3 + tx_;
                    // prefetch next tap's G (next nl's tap0 at tap==8; the
                    // very last prefetch of the chunk is a harmless dummy
                    // re-read of tap0 — overwritten by next chunk's preload)
                    const float* gn;
                    if (tap < 8)      gn = gp + (tap + 1) * 64;
                    else if (nl < 7)  gn = gp + 576;
                    else              gn = gp;            // dummy, safe
                    ulonglong2 N0 = *reinterpret_cast<const ulonglong2*>(gn + 0);
                    ulonglong2 N1 = *reinterpret_cast<const ulonglong2*>(gn + 4);
                    ulonglong2 N2 = *reinterpret_cast<const ulonglong2*>(gn + 8);
                    ulonglong2 N3 = *reinterpret_cast<const ulonglong2*>(gn + 12);
                    #pragma unroll
                    for (int j = 0; j < 4; ++j) {
                        const unsigned long long a = av[j + 2 - tx_];
                        ffma2(acc[j][0], a, C0.x); ffma2(acc[j][1], a, C0.y);
                        ffma2(acc[j][2], a, C1.x); ffma2(acc[j][3], a, C1.y);
                        ffma2(acc[j][4], a, C2.x); ffma2(acc[j][5], a, C2.y);
                        ffma2(acc[j][6], a, C3.x); ffma2(acc[j][7], a, C3.y);
                    }
                    C0 = N0; C1 = N1; C2 = N2; C3 = N3;
                }
            }
        }

        // ---- border correction accumulation (edge blocks only) ------------
        if (hE) {
            const float* __restrict__ C = top ? g_CT : g_CB;
            const int er = top ? 1 : 8;
            const int m = tid >> 1, p0 = (tid & 1) * 8;
            float c[8];
            #pragma unroll
            for (int k = 0; k < 8; ++k) c[k] = 0.0f;
            for (int j = 0; j < 3; ++j)
                #pragma unroll
                for (int nl = 0; nl < 8; ++nl) {
                    const float cv = C[j * 4096 + (ch0 + nl) * 64 + m];
                    const float* arow = &ash[nl * 210 + er * 21 + p0 + 2 - j];
                    #pragma unroll
                    for (int k = 0; k < 8; ++k) c[k] += cv * arow[k];
                }
            #pragma unroll
            for (int k = 0; k < 8; ++k) corrH[p0 + k][m] += c[k];
        }
        if (vE) {
            const float* __restrict__ C = lef ? g_CL : g_CR;
            const int ec = lef ? 1 : 8;
            const int m = tid >> 1, p0 = (tid & 1) * 4;
            float c0 = 0.f, c1 = 0.f, c2 = 0.f, c3 = 0.f;
            for (int j = 0; j < 3; ++j)
                #pragma unroll
                for (int nl = 0; nl < 8; ++nl) {
                    const float cv = C[j * 4096 + (ch0 + nl) * 64 + m];
                    const float* acol = &ash[nl * 210 + (p0 + 2 - j) * 21 + ec];
                    c0 += cv * acol[0];
                    c1 += cv * acol[21];
                    c2 += cv * acol[42];
                    c3 += cv * acol[63];
                }
            corrV[p0 + 0][m] += c0; corrV[p0 + 1][m] += c1;
            corrV[p0 + 2][m] += c2; corrV[p0 + 3][m] += c3;
        }
        if (hE && vE) {
            const int m = tid >> 1;
            const int half = tid & 1;
            const int want = rig ? 1 : 0;
            if (half == want) {
                const int c = (top ? 0 : 2) + (rig ? 1 : 0);
                const int rr = top ? 1 : 8, cc2 = lef ? 1 : 8;
                float s = 0.f;
                #pragma unroll
                for (int nl = 0; nl < 8; ++nl)
                    s += g_CO[c * 4096 + (ch0 + nl) * 64 + m]
                       * ash[nl * 210 + rr * 21 + cc2];
                corrH[rig ? 7 : 0][m] -= s;
            }
        }
    }
    __syncthreads();                                  // corr complete

    // ---- epilogue: fused u update + shrink ---------------------------------
    const int xg = tx0 + x0;                          // global x of quad start
    if (xg < 56) {
        float ga[4][16];
        #pragma unroll
        for (int j = 0; j < 4; ++j)
            #pragma unroll
            for (int c = 0; c < 8; ++c) {
                float2 t = unpk(acc[j][c]);
                ga[j][2 * c] = t.x; ga[j][2 * c + 1] = t.y;
            }

        if ((top && py == 0) || (bot && py == 7)) {
            #pragma unroll
            for (int j = 0; j < 4; ++j)
                #pragma unroll
                for (int mi = 0; mi < 16; ++mi)
                    ga[j][mi] -= corrH[x0 + j][m0 + mi];
        }
        if (lef && xq == 0) {
            #pragma unroll
            for (int mi = 0; mi < 16; ++mi) ga[0][mi] -= corrV[py][m0 + mi];
        }
        if (rig && xq == 1) {                         // local x 7 = global 55
            #pragma unroll
            for (int mi = 0; mi < 16; ++mi) ga[3][mi] -= corrV[py][m0 + mi];
        }

        const int y = ty0 + py;
        #pragma unroll
        for (int mi = 0; mi < 16; ++mi) {
            const size_t base = ((size_t)(bi * 64 + m0 + mi) * H + y) * W + xg;
            float4 u4 = *reinterpret_cast<const float4*>(&g_U[base]);
            float4 b4 = *reinterpret_cast<const float4*>(&g_B[base]);
            float4 un, an;
            un.x = u4.x + 0.1f * (b4.x - u4.x - ga[0][mi]);
            un.y = u4.y + 0.1f * (b4.y - u4.y - ga[1][mi]);
            un.z = u4.z + 0.1f * (b4.z - u4.z - ga[2][mi]);
            un.w = u4.w + 0.1f * (b4.w - u4.w - ga[3][mi]);
            an.x = shrinkf(un.x); an.y = shrinkf(un.y);
            an.z = shrinkf(un.z); an.w = shrinkf(un.w);
            *reinterpret_cast<float4*>(&g_U[base])   = un;
            *reinterpret_cast<float4*>(&a_out[base]) = an;
        }
    }
}

// ---------------------------------------------------------------------------
extern "C" void kernel_launch(void* const* d_in, const int* in_sizes, int n_in,
                              void* d_out, int out_size) {
    (void)in_sizes; (void)n_in; (void)out_size;
    const float* x    = (const float*)d_in[0];
    const float* dict = (const float*)d_in[1];
    float*       out  = (float*)d_out;

    lca_gram<<<25, 256>>>(dict);
    lca_b<<<dim3(28, 64), 128>>>(x, dict);

    // iterations 2..10; odd count -> final a lands in d_out
    for (int it = 0; it < 9; ++it)
        lca_iter<<<dim3(28, 64), 128>>>(out, it & 1);
}

// round 17
// speedup vs baseline: 1.1157x; 1.0475x over previous
#include <cuda_runtime.h>

// ---------------------------------------------------------------------------
// LCA layer on GB300 (FFMA2 path; tcgen05 unavailable: harness compiles
// device code as sm_103 without the 'a' suffix and ptxas rejects tcgen05).
//
// b = conv2d(x, D, s=4, p=2); 10x { inh = conv(convT(a)) - a;
//   u += 0.1*(b - u - inh); a = softshrink(u, 0.1) }
//
// conv∘convT == Gram operator: 3x3 taps, G[t][n][m] 64x64 per tap, center
// diag -1 folded. Boundary phantom products collapse to 1-D 3-tap edge Grams
// CT/CB/CL/CR + 4 corner overlaps CO, fused into lca_iter.
//
// lca_iter (v8): R14 tiling/math verbatim, but 4 chunks of 16 channels via
// dynamic smem (56448 B: gs 36864 + ash 13440 + corr 6144). Halves the
// chunk-boundary dead time (2 barriers + serial LDG->STS stage per chunk)
// identified as the residual between fma=61.5% and the 66% pipe floor.
// cudaFuncSetAttribute is called only when stream 0 is NOT capturing (the
// harness's correctness run sets it; capture replays skip the call).
// ---------------------------------------------------------------------------

#define NATOMS 64
#define BATCH  64
#define H 56
#define W 56
#define HW (H*W)
#define PLANE ((size_t)NATOMS * HW)

__device__ float g_B [BATCH * NATOMS * HW];
__device__ float g_U [BATCH * NATOMS * HW];
__device__ float g_A0[BATCH * NATOMS * HW];
__device__ float g_G [9 * 64 * 64];            // interior Gram [tap][n][m]
__device__ float g_CT[3 * 64 * 64];            // top edge, taps dx=-1,0,1
__device__ float g_CB[3 * 64 * 64];            // bottom
__device__ float g_CL[3 * 64 * 64];            // left,  taps dy=-1,0,1
__device__ float g_CR[3 * 64 * 64];            // right
__device__ float g_CO[4 * 64 * 64];            // corner overlaps TL,TR,BL,BR

// ---- packed f32x2 helpers --------------------------------------------------
__device__ __forceinline__ unsigned long long dup2(float x) {
    unsigned long long r;
    asm("mov.b64 %0, {%1, %1};" : "=l"(r) : "f"(x));
    return r;
}
__device__ __forceinline__ void ffma2(unsigned long long& d,
                                      unsigned long long a,
                                      unsigned long long b) {
    asm("fma.rn.f32x2 %0, %1, %2, %0;" : "+l"(d) : "l"(a), "l"(b));
}
__device__ __forceinline__ float2 unpk(unsigned long long v) {
    float2 r;
    asm("mov.b64 {%0, %1}, %2;" : "=f"(r.x), "=f"(r.y) : "l"(v));
    return r;
}
__device__ __forceinline__ float shrinkf(float u) {
    float mag = fabsf(u) - 0.1f;
    return mag > 0.0f ? copysignf(mag, u) : 0.0f;
}

// ---------------------------------------------------------------------------
// Gram kernel. 25 blocks: 0..8 interior taps, 9..20 edges, 21..24 corners.
// ---------------------------------------------------------------------------
__global__ void lca_gram(const float* __restrict__ dict) {
    __shared__ float ds[64 * 3 * 8 * 8];
    const int t   = blockIdx.x;
    const int tid = threadIdx.x;
    for (int e = tid; e < 12288; e += 256) ds[e] = dict[e];
    __syncthreads();

    if (t < 9) {
        const int dy = t / 3 - 1, dx = t % 3 - 1;
        const int kylo = dy < 0 ? 4 : 0, kyhi = dy > 0 ? 4 : 8;
        const int kxlo = dx < 0 ? 4 : 0, kxhi = dx > 0 ? 4 : 8;
        for (int e = tid; e < 4096; e += 256) {
            const int n = e >> 6, m = e & 63;
            float s = 0.0f;
            for (int i = 0; i < 3; ++i) {
                const float* dm = &ds[m * 192 + i * 64];
                const float* dn = &ds[n * 192 + i * 64 + 4 * dy * 8 + 4 * dx];
                for (int ky = kylo; ky < kyhi; ++ky)
                    #pragma unroll
                    for (int kx = kxlo; kx < kxhi; ++kx)
                        s += dm[ky * 8 + kx] * dn[ky * 8 + kx];
            }
            if (t == 4 && n == m) s -= 1.0f;
            g_G[t * 4096 + e] = s;
        }
    } else if (t < 21) {
        const int side = (t - 9) / 3;           // 0 top,1 bot,2 left,3 right
        const int j    = (t - 9) % 3;
        const int d    = j - 1;
        float* out = (side == 0 ? g_CT : side == 1 ? g_CB
                    : side == 2 ? g_CL : g_CR) + j * 4096;
        for (int e = tid; e < 4096; e += 256) {
            const int n = e >> 6, m = e & 63;
            float s = 0.0f;
            for (int i = 0; i < 3; ++i) {
                const float* dm = &ds[m * 192 + i * 64];
                const float* dn = &ds[n * 192 + i * 64];
                if (side < 2) {
                    const int ky0 = (side == 0) ? 0 : 6;
                    const int kxlo = d < 0 ? 4 : 0, kxhi = d > 0 ? 4 : 8;
                    for (int ky = ky0; ky < ky0 + 2; ++ky)
                        for (int kx = kxlo; kx < kxhi; ++kx)
                            s += dm[ky * 8 + kx] * dn[ky * 8 + kx + 4 * d];
                } else {
                    const int kx0 = (side == 2) ? 0 : 6;
                    const int kylo = d < 0 ? 4 : 0, kyhi = d > 0 ? 4 : 8;
                    for (int ky = kylo; ky < kyhi; ++ky)
                        for (int kx = kx0; kx < kx0 + 2; ++kx)
                            s += dm[ky * 8 + kx] * dn[(ky + 4 * d) * 8 + kx];
                }
            }
            out[e] = s;
        }
    } else {
        const int c   = t - 21;
        const int ky0 = (c < 2) ? 0 : 6;
        const int kx0 = (c & 1) ? 6 : 0;
        for (int e = tid; e < 4096; e += 256) {
            const int n = e >> 6, m = e & 63;
            float s = 0.0f;
            for (int i = 0; i < 3; ++i) {
                const float* dm = &ds[m * 192 + i * 64];
                const float* dn = &ds[n * 192 + i * 64];
                for (int ky = ky0; ky < ky0 + 2; ++ky)
                    for (int kx = kx0; kx < kx0 + 2; ++kx)
                        s += dm[ky * 8 + kx] * dn[ky * 8 + kx];
            }
            g_CO[c * 4096 + e] = s;
        }
    }
}

// ---------------------------------------------------------------------------
// b = conv2d(x, D, 4, 2), fused iter 1: u1 = 0.1*b, a1 = shrink(u1).
// (v2, passing: phase-split x-patch, warp-uniform dict.)
// ---------------------------------------------------------------------------
__global__ __launch_bounds__(128, 4)
void lca_b(const float* __restrict__ x, const float* __restrict__ dict) {
    __shared__ float xs[4 * 36 * 19];            // 10.7 KB (phase arrays)
    __shared__ float dt[64 * 68];                // 17.0 KB [kk][m] stride 68

    const int bi   = blockIdx.y;
    const int tile = blockIdx.x;                 // 0..27
    const int ty0  = (tile >> 2) * 8;
    const int tx0  = (tile & 3) * 16;
    const int tid  = threadIdx.x;
    const int w    = tid >> 5, l = tid & 31;
    const int m0   = w * 16;
    const int py   = l >> 2, xq = l & 3;

    unsigned long long acc[4][8];
    #pragma unroll
    for (int j = 0; j < 4; ++j)
        #pragma unroll
        for (int c = 0; c < 8; ++c) acc[j][c] = 0ull;

    for (int i = 0; i < 3; ++i) {
        __syncthreads();
        for (int e = tid; e < 4096; e += 128) {
            const int m = e >> 6, kk = e & 63;
            dt[kk * 68 + m] = dict[m * 192 + i * 64 + kk];
        }
        const int gy0 = 4 * ty0 - 2, gx0 = 4 * tx0 - 2;
        for (int e = tid; e < 2448; e += 128) {
            const int r = e / 68, cc = e - r * 68;
            const int gy = gy0 + r, gx = gx0 + cc;
            float v = 0.0f;
            if ((unsigned)gy < 224u && (unsigned)gx < 224u)
                v = x[((size_t)(bi * 3 + i) * 224 + gy) * 224 + gx];
            const int p  = (cc + 2) & 3;
            const int tc = (cc - 2 - p) / 4 + 1;
            xs[p * 684 + r * 19 + tc] = v;
        }
        __syncthreads();

        const float* xsp = xs + (4 * py) * 19 + xq + 1;
        for (int ky = 0; ky < 8; ++ky) {
            const float* xrow = xsp + ky * 19;
            #pragma unroll
            for (int kx = 0; kx < 8; ++kx) {
                const int p = (kx + 2) & 3;          // (kx-2) mod 4
                const int q = (kx < 2) ? -1 : (kx < 6) ? 0 : 1;
                const float* xr = xrow + p * 684 + q;
                const float* gt = &dt[(ky * 8 + kx) * 68 + m0]; // warp-uniform
                ulonglong2 H0 = *reinterpret_cast<const ulonglong2*>(gt + 0);
                ulonglong2 H1 = *reinterpret_cast<const ulonglong2*>(gt + 4);
                ulonglong2 H2 = *reinterpret_cast<const ulonglong2*>(gt + 8);
                ulonglong2 H3 = *reinterpret_cast<const ulonglong2*>(gt + 12);
                #pragma unroll
                for (int j = 0; j < 4; ++j) {
                    const unsigned long long a = dup2(xr[4 * j]);
                    ffma2(acc[j][0], a, H0.x); ffma2(acc[j][1], a, H0.y);
                    ffma2(acc[j][2], a, H1.x); ffma2(acc[j][3], a, H1.y);
                    ffma2(acc[j][4], a, H2.x); ffma2(acc[j][5], a, H2.y);
                    ffma2(acc[j][6], a, H3.x); ffma2(acc[j][7], a, H3.y);
                }
            }
        }
    }

    const int y = ty0 + py;
    #pragma unroll
    for (int j = 0; j < 4; ++j) {
        const int xg = tx0 + xq + 4 * j;
        if (xg < 56) {
            float bv[16];
            #pragma unroll
            for (int c = 0; c < 8; ++c) {
                float2 t = unpk(acc[j][c]);
                bv[2 * c] = t.x; bv[2 * c + 1] = t.y;
            }
            #pragma unroll
            for (int mm = 0; mm < 16; ++mm) {
                const size_t idx =
                    ((size_t)(bi * 64 + m0 + mm) * H + y) * W + xg;
                const float bb = bv[mm];
                const float un = 0.1f * bb;
                g_B[idx]  = bb;
                g_U[idx]  = un;
                g_A0[idx] = shrinkf(un);
            }
        }
    }
}

// ---------------------------------------------------------------------------
// One LCA iteration, fused border correction (v8: 4 chunks x 16 channels,
// dynamic smem 56448 B). Layout (floats):
//   gs   [0 .. 9216)    : [nl*9+tap][m], nl<16       36864 B
//   ash  [9216 .. 12576): [nl][10][21], cols<18      13440 B
//   corrH[12576 .. 13600): [16][64]                   4096 B
//   corrV[13600 .. 14112): [8][64]                    2048 B
// ---------------------------------------------------------------------------
#define ITER_SMEM_FLOATS 14112
#define ITER_SMEM_BYTES  (ITER_SMEM_FLOATS * 4)

__global__ __launch_bounds__(128, 4)
void lca_iter(float* __restrict__ a_ext, int mode) {
    extern __shared__ float sm[];
    float* gs    = sm;                            // 9216 floats
    float* ash   = sm + 9216;                     // 3360 floats
    float* corrH = sm + 12576;                    // 1024 floats [x][64]
    float* corrV = sm + 13600;                    // 512  floats [py][64]

    const float* __restrict__ a_in  = mode ? a_ext : g_A0;
    float* __restrict__       a_out = mode ? g_A0  : a_ext;

    const int bi   = blockIdx.y;
    const int tile = blockIdx.x;                 // 0..27
    const int ty0  = (tile >> 2) * 8;
    const int tx0  = (tile & 3) * 16;
    const int tid  = threadIdx.x;
    const int w    = tid >> 5, l = tid & 31;
    const int m0   = w * 16;
    const int py   = l >> 2, xq = l & 3, x0 = 4 * xq;

    const bool top = (ty0 == 0), bot = (ty0 == 48);
    const bool lef = (tx0 == 0), rig = (tx0 == 48);
    const bool hE = top || bot, vE = lef || rig;

    if (hE || vE) {
        for (int e = tid; e < 1024; e += 128) corrH[e] = 0.0f;
        for (int e = tid; e < 512;  e += 128) corrV[e] = 0.0f;
    }

    unsigned long long acc[4][8];
    #pragma unroll
    for (int j = 0; j < 4; ++j)
        #pragma unroll
        for (int c = 0; c < 8; ++c) acc[j][c] = 0ull;

    const float* abase = a_in + (size_t)bi * PLANE;

    for (int ck = 0; ck < 4; ++ck) {
        const int ch0 = ck * 16;
        __syncthreads();                              // prev chunk consumed
        // G slice [nl*9+tap][m], float4-staged, nl < 16
        for (int e = tid; e < 2304; e += 128) {
            const int m4 = e & 15, q = e >> 4;        // q = nl*9+tap, q<144
            const int nl = q / 9, tap = q - nl * 9;
            reinterpret_cast<float4*>(gs)[e] =
                reinterpret_cast<const float4*>(
                    g_G + tap * 4096 + (ch0 + nl) * 64)[m4];
        }
        // a halo: 10 rows x 18 cols per channel, zero outside image
        for (int e = tid; e < 2880; e += 128) {
            const int nl = e / 180, r2 = e - nl * 180;
            const int rr = r2 / 18, cc = r2 - rr * 18;
            const int gy = ty0 - 1 + rr, gx = tx0 - 1 + cc;
            float v = 0.0f;
            if ((unsigned)gy < (unsigned)H && (unsigned)gx < (unsigned)W)
                v = abase[(ch0 + nl) * HW + gy * W + gx];
            ash[nl * 210 + rr * 21 + cc] = v;
        }
        __syncthreads();

        for (int nl = 0; nl < 16; ++nl) {
            const float* ap = &ash[nl * 210 + py * 21 + x0];
            const float* gp = &gs[nl * 576 + m0];
            #pragma unroll
            for (int ty_ = 0; ty_ < 3; ++ty_) {
                unsigned long long av[6];
                const float* arow = ap + (2 - ty_) * 21;
                #pragma unroll
                for (int c = 0; c < 6; ++c) av[c] = dup2(arow[c]);
                #pragma unroll
                for (int tx_ = 0; tx_ < 3; ++tx_) {
                    const float* gt = gp + (ty_ * 3 + tx_) * 64; // warp-uniform
                    ulonglong2 H0 = *reinterpret_cast<const ulonglong2*>(gt + 0);
                    ulonglong2 H1 = *reinterpret_cast<const ulonglong2*>(gt + 4);
                    ulonglong2 H2 = *reinterpret_cast<const ulonglong2*>(gt + 8);
                    ulonglong2 H3 = *reinterpret_cast<const ulonglong2*>(gt + 12);
                    #pragma unroll
                    for (int j = 0; j < 4; ++j) {
                        const unsigned long long a = av[j + 2 - tx_];
                        ffma2(acc[j][0], a, H0.x); ffma2(acc[j][1], a, H0.y);
                        ffma2(acc[j][2], a, H1.x); ffma2(acc[j][3], a, H1.y);
                        ffma2(acc[j][4], a, H2.x); ffma2(acc[j][5], a, H2.y);
                        ffma2(acc[j][6], a, H3.x); ffma2(acc[j][7], a, H3.y);
                    }
                }
            }
        }

        // ---- border correction accumulation (edge blocks only) ------------
        if (hE) {
            const float* __restrict__ C = top ? g_CT : g_CB;
            const int er = top ? 1 : 8;
            const int m = tid >> 1, p0 = (tid & 1) * 8;
            float c[8];
            #pragma unroll
            for (int k = 0; k < 8; ++k) c[k] = 0.0f;
            for (int j = 0; j < 3; ++j)
                #pragma unroll
                for (int nl = 0; nl < 16; ++nl) {
                    const float cv = C[j * 4096 + (ch0 + nl) * 64 + m];
                    const float* arow = &ash[nl * 210 + er * 21 + p0 + 2 - j];
                    #pragma unroll
                    for (int k = 0; k < 8; ++k) c[k] += cv * arow[k];
                }
            #pragma unroll
            for (int k = 0; k < 8; ++k) corrH[(p0 + k) * 64 + m] += c[k];
        }
        if (vE) {
            const float* __restrict__ C = lef ? g_CL : g_CR;
            const int ec = lef ? 1 : 8;
            const int m = tid >> 1, p0 = (tid & 1) * 4;
            float c0 = 0.f, c1 = 0.f, c2 = 0.f, c3 = 0.f;
            for (int j = 0; j < 3; ++j)
                #pragma unroll
                for (int nl = 0; nl < 16; ++nl) {
                    const float cv = C[j * 4096 + (ch0 + nl) * 64 + m];
                    const float* acol = &ash[nl * 210 + (p0 + 2 - j) * 21 + ec];
                    c0 += cv * acol[0];
                    c1 += cv * acol[21];
                    c2 += cv * acol[42];
                    c3 += cv * acol[63];
                }
            corrV[(p0 + 0) * 64 + m] += c0; corrV[(p0 + 1) * 64 + m] += c1;
            corrV[(p0 + 2) * 64 + m] += c2; corrV[(p0 + 3) * 64 + m] += c3;
        }
        if (hE && vE) {
            const int m = tid >> 1;
            const int half = tid & 1;
            const int want = rig ? 1 : 0;
            if (half == want) {
                const int c = (top ? 0 : 2) + (rig ? 1 : 0);
                const int rr = top ? 1 : 8, cc2 = lef ? 1 : 8;
                float s = 0.f;
                #pragma unroll
                for (int nl = 0; nl < 16; ++nl)
                    s += g_CO[c * 4096 + (ch0 + nl) * 64 + m]
                       * ash[nl * 210 + rr * 21 + cc2];
                corrH[(rig ? 7 : 0) * 64 + m] -= s;
            }
        }
    }
    __syncthreads();                                  // corr complete

    // ---- epilogue: fused u update + shrink ---------------------------------
    const int xg = tx0 + x0;                          // global x of quad start
    if (xg < 56) {
        float ga[4][16];
        #pragma unroll
        for (int j = 0; j < 4; ++j)
            #pragma unroll
            for (int c = 0; c < 8; ++c) {
                float2 t = unpk(acc[j][c]);
                ga[j][2 * c] = t.x; ga[j][2 * c + 1] = t.y;
            }

        if ((top && py == 0) || (bot && py == 7)) {
            #pragma unroll
            for (int j = 0; j < 4; ++j)
                #pragma unroll
                for (int mi = 0; mi < 16; ++mi)
                    ga[j][mi] -= corrH[(x0 + j) * 64 + m0 + mi];
        }
        if (lef && xq == 0) {
            #pragma unroll
            for (int mi = 0; mi < 16; ++mi)
                ga[0][mi] -= corrV[py * 64 + m0 + mi];
        }
        if (rig && xq == 1) {                         // local x 7 = global 55
            #pragma unroll
            for (int mi = 0; mi < 16; ++mi)
                ga[3][mi] -= corrV[py * 64 + m0 + mi];
        }

        const int y = ty0 + py;
        #pragma unroll
        for (int mi = 0; mi < 16; ++mi) {
            const size_t base = ((size_t)(bi * 64 + m0 + mi) * H + y) * W + xg;
            float4 u4 = *reinterpret_cast<const float4*>(&g_U[base]);
            float4 b4 = *reinterpret_cast<const float4*>(&g_B[base]);
            float4 un, an;
            un.x = u4.x + 0.1f * (b4.x - u4.x - ga[0][mi]);
            un.y = u4.y + 0.1f * (b4.y - u4.y - ga[1][mi]);
            un.z = u4.z + 0.1f * (b4.z - u4.z - ga[2][mi]);
            un.w = u4.w + 0.1f * (b4.w - u4.w - ga[3][mi]);
            an.x = shrinkf(un.x); an.y = shrinkf(un.y);
            an.z = shrinkf(un.z); an.w = shrinkf(un.w);
            *reinterpret_cast<float4*>(&g_U[base])   = un;
            *reinterpret_cast<float4*>(&a_out[base]) = an;
        }
    }
}

// ---------------------------------------------------------------------------
extern "C" void kernel_launch(void* const* d_in, const int* in_sizes, int n_in,
                              void* d_out, int out_size) {
    (void)in_sizes; (void)n_in; (void)out_size;
    const float* x    = (const float*)d_in[0];
    const float* dict = (const float*)d_in[1];
    float*       out  = (float*)d_out;

    // Raise lca_iter's dynamic-smem limit. Only legal outside graph capture;
    // the harness's correctness run (uncaptured) sets it, replays skip it.
    // Same GPU work is enqueued on every call.
    cudaStreamCaptureStatus st = cudaStreamCaptureStatusNone;
    cudaStreamIsCapturing((cudaStream_t)0, &st);
    if (st == cudaStreamCaptureStatusNone)
        cudaFuncSetAttribute(lca_iter,
                             cudaFuncAttributeMaxDynamicSharedMemorySize,
                             ITER_SMEM_BYTES);

    lca_gram<<<25, 256>>>(dict);
    lca_b<<<dim3(28, 64), 128>>>(x, dict);

    // iterations 2..10; odd count -> final a lands in d_out
    for (int it = 0; it < 9; ++it)
        lca_iter<<<dim3(28, 64), 128, ITER_SMEM_BYTES>>>(out, it & 1);
}